// round 12
// baseline (speedup 1.0000x reference)
#include <cuda_runtime.h>
#include <cstdint>

// knnLoss:  loss = sum_{b,t} min_s ||s-t||^2 / 120000  (exact).
// memset -> pack (bin sources per cell, bin targets per 2x2x2 supercell)
//        -> search: one block per (supercell, split); block stages the
//           supercell+-1 cell union into smem, warps process 32 targets each
//           with BROADCAST smem loads (zero divergence). Exact bound: any
//           source in an unscanned cell is >= h away (holds under clamping);
//           best <= 0.9995 h^2 proves the min, else warp-brute fallback.

#define OUT_HW   100
#define STRIDE   4
#define NPTS     10000
#define NB       4
#define NBNPTS   (NB * NPTS)
#define HW       400
#define PLANE    (HW * HW)
#define NALL     (2 * NBNPTS)
#define G        16
#define G3       (G * G * G)
#define GS       8                    // supercells per dim
#define NSCB     (GS * GS * GS)       // 512 per batch
#define NSC      (NB * NSCB)          // 2048
#define NSEG     (NB * G3)            // 16384 source cells
#define CAP      96                   // source pts per cell
#define SC_CAP   512                  // targets per supercell
#define RANGE    3.2f
#define HCELL    0.4f
#define INVH     2.5f
#define HBOUND   (0.9995f * HCELL * HCELL)
#define FINF     3.4e38f
#define NOVF_MAX 2048
#define SMAX     2688                 // staged union pts (43KB)

#define SPLIT    2
#define SBLK     (NSC * SPLIT)        // 4096
#define STHR     256

// zero region layout
#define ZSRC   0
#define ZTGT   NSEG
#define ZOVF   (NSEG + NSC)
#define ZFBT   (NSEG + NSC + 1)
#define ZDONE  (NSEG + NSC + 2)
#define ZN     (NSEG + NSC + 3)

__device__ int    g_zero[ZN];
__device__ float4 g_bins[NSEG * CAP];       // source cell bins
__device__ float4 g_tbins[NSC * SC_CAP];    // target supercell bins
__device__ float4 g_sflat[NBNPTS];          // flat sources (fallback scans)
__device__ float4 g_ovf[NOVF_MAX];          // source cell overflow
__device__ int    g_ovfb[NOVF_MAX];
__device__ float4 g_fbt[NOVF_MAX];          // target supercell overflow
__device__ int    g_fbtb[NOVF_MAX];
__device__ float  g_bpart[SBLK];

// ---------------------------------------------------------------------------
__global__ void __launch_bounds__(256)
pack_kernel(const float* __restrict__ tgt, const float* __restrict__ src) {
    int i = blockIdx.x * blockDim.x + threadIdx.x;
    if (i >= NALL) return;
    int which = i / NBNPTS;               // 0 = source, 1 = target
    int r = i - which * NBNPTS;
    int b = r / NPTS;
    int m = r - b * NPTS;
    int h = (m / OUT_HW) * STRIDE;
    int w = (m - (m / OUT_HW) * OUT_HW) * STRIDE;
    const float* p = (which == 0 ? src : tgt) + (size_t)b * 3 * PLANE + h * HW + w;
    float x = p[0];
    float y = p[PLANE];
    float z = p[2 * PLANE];
    float4 v = make_float4(x, y, z, fmaf(x, x, fmaf(y, y, z * z)));

    int cx = min(max((int)floorf((x + RANGE) * INVH), 0), G - 1);
    int cy = min(max((int)floorf((y + RANGE) * INVH), 0), G - 1);
    int cz = min(max((int)floorf((z + RANGE) * INVH), 0), G - 1);

    if (which == 0) {
        g_sflat[r] = v;
        int cell = b * G3 + (cz * G + cy) * G + cx;
        int rank = atomicAdd(&g_zero[ZSRC + cell], 1);
        if (rank < CAP) {
            g_bins[cell * CAP + rank] = v;
        } else {
            int o = atomicAdd(&g_zero[ZOVF], 1);
            if (o < NOVF_MAX) { g_ovf[o] = v; g_ovfb[o] = b; }
        }
    } else {
        int sc = b * NSCB + ((cz >> 1) * GS + (cy >> 1)) * GS + (cx >> 1);
        int rank = atomicAdd(&g_zero[ZTGT + sc], 1);
        if (rank < SC_CAP) {
            g_tbins[sc * SC_CAP + rank] = v;
        } else {
            int o = atomicAdd(&g_zero[ZFBT], 1);
            if (o < NOVF_MAX) { g_fbt[o] = v; g_fbtb[o] = b; }
        }
    }
}

// ---------------------------------------------------------------------------
__global__ void __launch_bounds__(STHR)
search_kernel(float* __restrict__ out) {
    __shared__ float4 spts[SMAX];
    __shared__ int    scn[64];
    __shared__ float  red[STHR];
    __shared__ int    slast;

    int tid  = threadIdx.x;
    int wid  = tid >> 5;
    int lane = tid & 31;
    int sc    = blockIdx.x >> 1;
    int split = blockIdx.x & 1;
    int b   = sc >> 9;
    int s   = sc & (NSCB - 1);
    int scx = s & 7, scy = (s >> 3) & 7, scz = s >> 6;

    int ntgt = min(g_zero[ZTGT + sc], SC_CAP);
    float lsum = 0.0f;
    bool work = (ntgt > 32 * split);      // chunk `split` exists?

    if (work) {
        // union cell box = supercell +- 1 cell
        int x0 = max(2 * scx - 1, 0), x1 = min(2 * scx + 2, G - 1);
        int y0 = max(2 * scy - 1, 0), y1 = min(2 * scy + 2, G - 1);
        int z0 = max(2 * scz - 1, 0), z1 = min(2 * scz + 2, G - 1);
        int nx = x1 - x0 + 1, ny = y1 - y0 + 1, nz = z1 - z0 + 1;
        int ncell = nx * ny * nz;         // <= 64
        int segbase = b * G3;

        // cell counts -> exclusive offsets (Hillis-Steele over 64 slots)
        int mycnt = 0, mycell = 0;
        if (tid < 64) {
            if (tid < ncell) {
                int cz = z0 + tid / (nx * ny);
                int rem = tid - (tid / (nx * ny)) * (nx * ny);
                int cy = y0 + rem / nx;
                int cx = x0 + rem - (rem / nx) * nx;
                mycell = segbase + (cz * G + cy) * G + cx;
                mycnt = min(g_zero[ZSRC + mycell], CAP);
            }
            scn[tid] = mycnt;
        }
        __syncthreads();
        #pragma unroll
        for (int st = 1; st < 64; st <<= 1) {
            int a = 0;
            if (tid < 64 && tid >= st) a = scn[tid - st];
            __syncthreads();
            if (tid < 64) scn[tid] += a;
            __syncthreads();
        }
        int total = scn[63];
        bool staged = (total <= SMAX);

        if (staged) {
            // copy: 4 threads per cell (64 cells x 4 = 256)
            int ci = tid >> 2;
            if (ci < ncell) {
                int cz = z0 + ci / (nx * ny);
                int rem = ci - (ci / (nx * ny)) * (nx * ny);
                int cy = y0 + rem / nx;
                int cx = x0 + rem - (rem / nx) * nx;
                int cell = segbase + (cz * G + cy) * G + cx;
                int n = min(g_zero[ZSRC + cell], CAP);
                int off = scn[ci] - n;               // exclusive
                const float4* bp = g_bins + cell * CAP;
                for (int p = (tid & 3); p < n; p += 4)
                    spts[off + p] = bp[p];
            }
        }
        __syncthreads();

        int novf = min(g_zero[ZOVF], NOVF_MAX);

        // warps take chunks: split, split+2, ... interleaved over 8 warps
        for (int c = split + 2 * wid; c * 32 < ntgt; c += 2 * 8) {
            int ti = c * 32 + lane;
            bool act = ti < ntgt;
            float4 tv = act ? g_tbins[sc * SC_CAP + ti]
                            : make_float4(0.f, 0.f, 0.f, 0.f);
            float ax = -2.0f * tv.x, ay = -2.0f * tv.y, az = -2.0f * tv.z;
            float best = FINF;

            if (staged) {
                int p = 0;
                for (; p + 4 <= total; p += 4) {
                    float4 s0 = spts[p + 0];
                    float4 s1 = spts[p + 1];
                    float4 s2 = spts[p + 2];
                    float4 s3 = spts[p + 3];
                    float d0 = fmaf(s0.x, ax, fmaf(s0.y, ay, fmaf(s0.z, az, s0.w)));
                    float d1 = fmaf(s1.x, ax, fmaf(s1.y, ay, fmaf(s1.z, az, s1.w)));
                    float d2 = fmaf(s2.x, ax, fmaf(s2.y, ay, fmaf(s2.z, az, s2.w)));
                    float d3 = fmaf(s3.x, ax, fmaf(s3.y, ay, fmaf(s3.z, az, s3.w)));
                    best = fminf(best, fminf(fminf(d0, d1), fminf(d2, d3)));
                }
                for (; p < total; p++) {
                    float4 s0 = spts[p];
                    best = fminf(best,
                        fmaf(s0.x, ax, fmaf(s0.y, ay, fmaf(s0.z, az, s0.w))));
                }
            } else {
                // rare: scan cells straight from gmem (uniform loads)
                for (int ci = 0; ci < ncell; ci++) {
                    int cz = z0 + ci / (nx * ny);
                    int rem = ci - (ci / (nx * ny)) * (nx * ny);
                    int cy = y0 + rem / nx;
                    int cx = x0 + rem - (rem / nx) * nx;
                    int cell = segbase + (cz * G + cy) * G + cx;
                    int n = min(g_zero[ZSRC + cell], CAP);
                    const float4* bp = g_bins + cell * CAP;
                    for (int p = 0; p < n; p++) {
                        float4 s0 = bp[p];
                        best = fminf(best,
                            fmaf(s0.x, ax, fmaf(s0.y, ay, fmaf(s0.z, az, s0.w))));
                    }
                }
            }
            // source-overflow points (normally zero)
            for (int o = 0; o < novf; o++) {
                if (g_ovfb[o] == b) {
                    float4 s0 = g_ovf[o];
                    best = fminf(best,
                        fmaf(s0.x, ax, fmaf(s0.y, ay, fmaf(s0.z, az, s0.w))));
                }
            }
            float full = best + tv.w;

            // bound unproven -> warp-cooperative exact brute scan
            unsigned need = __ballot_sync(0xffffffffu, act && (full > HBOUND));
            while (need) {
                int sl = __ffs(need) - 1;
                need &= need - 1;
                float bx = __shfl_sync(0xffffffffu, ax, sl);
                float by = __shfl_sync(0xffffffffu, ay, sl);
                float bz = __shfl_sync(0xffffffffu, az, sl);
                const float4* sp = g_sflat + b * NPTS;
                float mb = FINF;
                for (int p = lane; p < NPTS; p += 32) {
                    float4 s0 = sp[p];
                    mb = fminf(mb,
                        fmaf(s0.x, bx, fmaf(s0.y, by, fmaf(s0.z, bz, s0.w))));
                }
                #pragma unroll
                for (int o = 16; o > 0; o >>= 1)
                    mb = fminf(mb, __shfl_xor_sync(0xffffffffu, mb, o));
                float tw = __shfl_sync(0xffffffffu, tv.w, sl);
                if (lane == sl) full = mb + tw;
            }
            if (act) lsum += full;
        }
    }

    // block 0: overflowed targets (rare/none) -> warp brute, spread over warps
    if (blockIdx.x == 0) {
        int nfbt = min(g_zero[ZFBT], NOVF_MAX);
        for (int e = wid; e < nfbt; e += 8) {
            float4 tv = g_fbt[e];
            int bb = g_fbtb[e];
            float bx = -2.0f * tv.x, by = -2.0f * tv.y, bz = -2.0f * tv.z;
            const float4* sp = g_sflat + bb * NPTS;
            float mb = FINF;
            for (int p = lane; p < NPTS; p += 32) {
                float4 s0 = sp[p];
                mb = fminf(mb, fmaf(s0.x, bx, fmaf(s0.y, by, fmaf(s0.z, bz, s0.w))));
            }
            #pragma unroll
            for (int o = 16; o > 0; o >>= 1)
                mb = fminf(mb, __shfl_xor_sync(0xffffffffu, mb, o));
            if (lane == 0) lsum += mb + tv.w;
        }
    }

    // block reduce
    red[tid] = lsum;
    __syncthreads();
    #pragma unroll
    for (int st = STHR / 2; st > 0; st >>= 1) {
        if (tid < st) red[tid] += red[tid + st];
        __syncthreads();
    }
    if (tid == 0) {
        g_bpart[blockIdx.x] = red[0];
        __threadfence();
        slast = (atomicAdd(&g_zero[ZDONE], 1) == SBLK - 1);
    }
    __syncthreads();

    if (slast) {
        float ssum = 0.0f;
        for (int i = tid; i < SBLK; i += STHR) ssum += g_bpart[i];
        red[tid] = ssum;
        __syncthreads();
        #pragma unroll
        for (int st = STHR / 2; st > 0; st >>= 1) {
            if (tid < st) red[tid] += red[tid + st];
            __syncthreads();
        }
        if (tid == 0)
            out[0] = red[0] * (1.0f / (float)(NBNPTS * 3));
    }
}

// ---------------------------------------------------------------------------
extern "C" void kernel_launch(void* const* d_in, const int* in_sizes, int n_in,
                              void* d_out, int out_size) {
    const float* tgt = (const float*)d_in[0];   // target_pc (4,3,400,400)
    const float* src = (const float*)d_in[1];   // source_pc (4,3,400,400)
    float* out = (float*)d_out;

    void* zaddr = nullptr;
    cudaGetSymbolAddress(&zaddr, g_zero);
    cudaMemsetAsync(zaddr, 0, ZN * sizeof(int));

    pack_kernel<<<(NALL + 255) / 256, 256>>>(tgt, src);
    search_kernel<<<SBLK, STHR>>>(out);
}